// round 4
// baseline (speedup 1.0000x reference)
#include <cuda_runtime.h>
#include <utility>
#include <cstddef>

// Problem constants (fixed by the reference: N_COLS=16, ADD=3)
#define NC     16         // input columns
#define NTOT   696        // 16 + C(16,2)=120 + C(16,3)=560
#define NTOT4  174        // NTOT / 4 (output row in float4 units)
#define TPB    128        // threads per block == rows per tile
#define TILES  2          // row-tiles per block (balanced single-wave residency)
#define WROWS  32         // rows per warp (one row per lane)
#define SPAD4  9          // warp-subtile row stride in float4 units
// stride 9 f4 = 36 words == 4 (mod 32): conflict-free for both STS.128 and
// LDS.128 under the 8-lane-per-subphase shared-memory datapath.

// Streaming (evict-first) 128-bit global store: output is write-once,
// never re-read -> keep it out of L2's way.
__device__ __forceinline__ void stg_cs(float4* p, float4 v) {
    asm volatile("st.global.cs.v4.f32 [%0], {%1, %2, %3, %4};"
                 :: "l"(p), "f"(v.x), "f"(v.y), "f"(v.z), "f"(v.w) : "memory");
}

// Compile-time decode of output column g -> (i, j, k) subset indices.
// sel: 0 -> i, 1 -> j, 2 -> k.  Returns NC (=16) as "unused" sentinel.
__host__ __device__ constexpr int decode(int g, int sel) {
    if (g < NC) return sel == 0 ? g : NC;          // passthrough columns
    g -= NC;
    if (g < 120) {                                  // pairs, lexicographic
        int c = 0;
        for (int a = 0; a < NC; a++)
            for (int b = a + 1; b < NC; b++) {
                if (c == g) return sel == 0 ? a : (sel == 1 ? b : NC);
                c++;
            }
    } else {                                        // triples, lexicographic
        g -= 120;
        int c = 0;
        for (int a = 0; a < NC; a++)
            for (int b = a + 1; b < NC; b++)
                for (int d = b + 1; d < NC; d++) {
                    if (c == g) return sel == 0 ? a : (sel == 1 ? b : d);
                    c++;
                }
    }
    return NC;
}

// One output term with fully compile-time indices -> v[] stays in registers.
// Association (v[i]*v[j])*v[k] lets ptxas CSE the pair product across the
// lexicographic run of triples sharing (i, j).
template <int G>
__device__ __forceinline__ float term(const float (&v)[NC]) {
    constexpr int i = decode(G, 0);
    constexpr int j = decode(G, 1);
    constexpr int k = decode(G, 2);
    float r = v[i];
    if constexpr (j < NC) r = r * v[j];
    if constexpr (k < NC) r = r * v[k];
    return r;
}

// Lane computes its own row's float4 columns [C04, C04+NF4) into the warp's
// private subtile at sw[lane * SPAD4 + c].
template <int C04, int NF4, int... I>
__device__ __forceinline__ void compute_chunk(const float (&v)[NC], float4* sw, int lane,
                                              std::integer_sequence<int, I...>) {
    ((sw[lane * SPAD4 + I] = make_float4(term<4 * (C04 + I) + 0>(v),
                                         term<4 * (C04 + I) + 1>(v),
                                         term<4 * (C04 + I) + 2>(v),
                                         term<4 * (C04 + I) + 3>(v))), ...);
}

// Warp-local phase: compute -> syncwarp -> coalesced copy -> syncwarp.
// Copy mapping over the 32 x NF4 subtile: lin = k*32 + lane, r = lin / NF4,
// c = lin % NF4 (compile-time NF4 -> mul/shift, no divide). Lanes sharing a
// row are consecutive in c -> dense 16B-granular STG.128 runs; LDS.128
// conflict-free per the stride-9 analysis above.
template <int C04, int NF4>
__device__ __forceinline__ void process_chunk(const float (&v)[NC], float4* sw, int lane,
                                              float4* __restrict__ owarp) {
    compute_chunk<C04, NF4>(v, sw, lane, std::make_integer_sequence<int, NF4>{});
    __syncwarp();
#pragma unroll
    for (int k = 0; k < NF4; k++) {
        int lin = k * 32 + lane;
        int r   = lin / NF4;
        int c   = lin - r * NF4;
        stg_cs(&owarp[(size_t)r * NTOT4 + (C04 + c)], sw[r * SPAD4 + c]);
    }
    __syncwarp();
}

// One 128-row tile for this block.
__device__ __forceinline__ void do_tile(const float* __restrict__ x,
                                        float4* __restrict__ out4,
                                        float4* sw, size_t row0, int tid, int lane, int warp) {
    float v[NC];
    {
        const float4* xp = reinterpret_cast<const float4*>(x) + (row0 + tid) * (NC / 4);
        float4 a = xp[0], b = xp[1], c = xp[2], d = xp[3];
        v[0]  = a.x; v[1]  = a.y; v[2]  = a.z; v[3]  = a.w;
        v[4]  = b.x; v[5]  = b.y; v[6]  = b.z; v[7]  = b.w;
        v[8]  = c.x; v[9]  = c.y; v[10] = c.z; v[11] = c.w;
        v[12] = d.x; v[13] = d.y; v[14] = d.z; v[15] = d.w;
    }

    float4* owarp = out4 + (row0 + (size_t)warp * WROWS) * NTOT4;

    // 21 phases of 8 float4 columns + final 6  (21*8 + 6 = 174 = 696/4)
    process_chunk<  0, 8>(v, sw, lane, owarp);
    process_chunk<  8, 8>(v, sw, lane, owarp);
    process_chunk< 16, 8>(v, sw, lane, owarp);
    process_chunk< 24, 8>(v, sw, lane, owarp);
    process_chunk< 32, 8>(v, sw, lane, owarp);
    process_chunk< 40, 8>(v, sw, lane, owarp);
    process_chunk< 48, 8>(v, sw, lane, owarp);
    process_chunk< 56, 8>(v, sw, lane, owarp);
    process_chunk< 64, 8>(v, sw, lane, owarp);
    process_chunk< 72, 8>(v, sw, lane, owarp);
    process_chunk< 80, 8>(v, sw, lane, owarp);
    process_chunk< 88, 8>(v, sw, lane, owarp);
    process_chunk< 96, 8>(v, sw, lane, owarp);
    process_chunk<104, 8>(v, sw, lane, owarp);
    process_chunk<112, 8>(v, sw, lane, owarp);
    process_chunk<120, 8>(v, sw, lane, owarp);
    process_chunk<128, 8>(v, sw, lane, owarp);
    process_chunk<136, 8>(v, sw, lane, owarp);
    process_chunk<144, 8>(v, sw, lane, owarp);
    process_chunk<152, 8>(v, sw, lane, owarp);
    process_chunk<160, 8>(v, sw, lane, owarp);
    process_chunk<168, 6>(v, sw, lane, owarp);
}

__global__ void __launch_bounds__(TPB, 7)
algebraic_kernel(const float* __restrict__ x, float4* __restrict__ out4) {
    // 4 warps x 32 rows x 9 f4 x 16 B = 18,432 B; 7 blocks/SM -> 129 KB
    __shared__ float4 s4[4][WROWS * SPAD4];

    const int tid  = threadIdx.x;
    const int lane = tid & 31;
    const int warp = tid >> 5;
    float4* sw = s4[warp];

    // Balanced residency: grid = 1024 <= 148 SM * 7 blocks, every block
    // resident from t=0, each processes exactly TILES=2 row-tiles.
#pragma unroll
    for (int t = 0; t < TILES; t++) {
        const size_t row0 = ((size_t)blockIdx.x + (size_t)t * gridDim.x) * TPB;
        do_tile(x, out4, sw, row0, tid, lane, warp);
    }
}

extern "C" void kernel_launch(void* const* d_in, const int* in_sizes, int n_in,
                              void* d_out, int out_size) {
    const float* x    = (const float*)d_in[0];
    float4*      out4 = (float4*)d_out;
    const int nrows   = in_sizes[0] / NC;              // 262144
    const int blocks  = nrows / (TPB * TILES);         // 1024
    algebraic_kernel<<<blocks, TPB>>>(x, out4);
}

// round 5
// speedup vs baseline: 1.8360x; 1.8360x over previous
#include <cuda_runtime.h>
#include <cuda.h>          // CUtensorMap type (header-only use; symbol via runtime lookup)
#include <utility>
#include <cstddef>
#include <cstdint>

// Problem constants (fixed by the reference: N_COLS=16, ADD=3)
#define NC      16         // input columns
#define NTOT    696        // 16 + C(16,2)=120 + C(16,3)=560
#define NTOT4   174        // NTOT / 4
#define TPB     128        // threads per block == rows per tile
#define CCOLS   24         // output columns per TMA chunk (29 * 24 = 696)
#define NCHUNKS 29
#define CF4     6          // float4s per chunk per row
#define SPAN    128        // SW128 swizzle span = smem row pitch (bytes)
#define BUFB    (TPB * SPAN)   // 16 KB per buffer

// ---------------------------------------------------------------------------
// Compile-time decode of output column g -> (i, j, k) subset indices.
// sel: 0 -> i, 1 -> j, 2 -> k.  Returns NC (=16) as "unused" sentinel.
__host__ __device__ constexpr int decode(int g, int sel) {
    if (g < NC) return sel == 0 ? g : NC;           // passthrough columns
    g -= NC;
    if (g < 120) {                                   // pairs, lexicographic
        int c = 0;
        for (int a = 0; a < NC; a++)
            for (int b = a + 1; b < NC; b++) {
                if (c == g) return sel == 0 ? a : (sel == 1 ? b : NC);
                c++;
            }
    } else {                                         // triples, lexicographic
        g -= 120;
        int c = 0;
        for (int a = 0; a < NC; a++)
            for (int b = a + 1; b < NC; b++)
                for (int d = b + 1; d < NC; d++) {
                    if (c == g) return sel == 0 ? a : (sel == 1 ? b : d);
                    c++;
                }
    }
    return NC;
}

// One output term; compile-time indices keep v[] in registers, association
// (v[i]*v[j])*v[k] lets ptxas CSE pair products across lexicographic runs.
template <int G>
__device__ __forceinline__ float term(const float (&v)[NC]) {
    constexpr int i = decode(G, 0);
    constexpr int j = decode(G, 1);
    constexpr int k = decode(G, 2);
    float r = v[i];
    if constexpr (j < NC) r = r * v[j];
    if constexpr (k < NC) r = r * v[k];
    return r;
}

__device__ __forceinline__ uint32_t smem_u32(const void* p) {
    uint32_t a;
    asm("{ .reg .u64 t; cvta.to.shared.u64 t, %1; cvt.u32.u64 %0, t; }" : "=r"(a) : "l"(p));
    return a;
}

// Thread tid writes its row's 6 float4 for chunk C into the SW128-swizzled
// tile: row pitch 128 B, logical atom I lands at physical atom I^(tid&7).
// STS.128: within each 8-lane subphase the atoms are a permutation of 0..7
// -> conflict-free.
template <int C, int... I>
__device__ __forceinline__ void compute_chunk(const float (&v)[NC], char* buf, int tid,
                                              std::integer_sequence<int, I...>) {
    ((*reinterpret_cast<float4*>(buf + tid * SPAN + ((I ^ (tid & 7)) << 4)) =
          make_float4(term<C * CCOLS + 4 * I + 0>(v),
                      term<C * CCOLS + 4 * I + 1>(v),
                      term<C * CCOLS + 4 * I + 2>(v),
                      term<C * CCOLS + 4 * I + 3>(v))), ...);
}

// One pipelined chunk: reclaim buffer (TMA smem-read done) -> compute ->
// async-proxy fence -> barrier -> single-thread TMA 2D store + commit.
template <int C>
__device__ __forceinline__ void do_chunk(const float (&v)[NC], char* sbase, int tid,
                                         const CUtensorMap* pmap, int row0) {
    char* buf = sbase + (C & 1) * BUFB;
    if constexpr (C >= 2) {
        if (tid == 0)
            asm volatile("cp.async.bulk.wait_group.read 1;" ::: "memory");
        __syncthreads();
    }
    compute_chunk<C>(v, buf, tid, std::make_integer_sequence<int, CF4>{});
    asm volatile("fence.proxy.async.shared::cta;" ::: "memory");
    __syncthreads();
    if (tid == 0) {
        uint32_t saddr = smem_u32(buf);
        asm volatile(
            "cp.async.bulk.tensor.2d.global.shared::cta.tile.bulk_group [%0, {%1, %2}], [%3];"
            :: "l"(pmap), "r"(C * CCOLS), "r"(row0), "r"(saddr) : "memory");
        asm volatile("cp.async.bulk.commit_group;" ::: "memory");
    }
}

template <int... Cs>
__device__ __forceinline__ void do_all_chunks(const float (&v)[NC], char* sbase, int tid,
                                              const CUtensorMap* pmap, int row0,
                                              std::integer_sequence<int, Cs...>) {
    (do_chunk<Cs>(v, sbase, tid, pmap, row0), ...);
}

__global__ void __launch_bounds__(TPB)
algebraic_tma_kernel(const float* __restrict__ x, const __grid_constant__ CUtensorMap tmap) {
    extern __shared__ char sbuf[];            // 2 x 16 KB, dynamic -> span-aligned base

    const int tid  = threadIdx.x;
    const int row0 = blockIdx.x * TPB;

    float v[NC];
    {
        const float4* xp = reinterpret_cast<const float4*>(x) +
                           ((size_t)row0 + tid) * (NC / 4);
        float4 a = xp[0], b = xp[1], c = xp[2], d = xp[3];
        v[0]  = a.x; v[1]  = a.y; v[2]  = a.z; v[3]  = a.w;
        v[4]  = b.x; v[5]  = b.y; v[6]  = b.z; v[7]  = b.w;
        v[8]  = c.x; v[9]  = c.y; v[10] = c.z; v[11] = c.w;
        v[12] = d.x; v[13] = d.y; v[14] = d.z; v[15] = d.w;
    }

    do_all_chunks(v, sbuf, tid, &tmap, row0, std::make_integer_sequence<int, NCHUNKS>{});

    if (tid == 0)
        asm volatile("cp.async.bulk.wait_group 0;" ::: "memory");
}

// ---------------------------------------------------------------------------
// Fallback (only if tensormap creation is unavailable): direct strided stores.
template <int... I>
__device__ __forceinline__ void store_all(const float (&v)[NC], float4* __restrict__ o,
                                          std::integer_sequence<int, I...>) {
    ((o[I] = make_float4(term<4 * I + 0>(v), term<4 * I + 1>(v),
                         term<4 * I + 2>(v), term<4 * I + 3>(v))), ...);
}

__global__ void __launch_bounds__(TPB)
algebraic_fallback_kernel(const float* __restrict__ x, float4* __restrict__ out4) {
    const size_t row = (size_t)blockIdx.x * TPB + threadIdx.x;
    float v[NC];
    const float4* xp = reinterpret_cast<const float4*>(x) + row * (NC / 4);
    float4 a = xp[0], b = xp[1], c = xp[2], d = xp[3];
    v[0]  = a.x; v[1]  = a.y; v[2]  = a.z; v[3]  = a.w;
    v[4]  = b.x; v[5]  = b.y; v[6]  = b.z; v[7]  = b.w;
    v[8]  = c.x; v[9]  = c.y; v[10] = c.z; v[11] = c.w;
    v[12] = d.x; v[13] = d.y; v[14] = d.z; v[15] = d.w;
    store_all(v, out4 + row * NTOT4, std::make_integer_sequence<int, NTOT4>{});
}

// ---------------------------------------------------------------------------
extern "C" void kernel_launch(void* const* d_in, const int* in_sizes, int n_in,
                              void* d_out, int out_size) {
    const float* x  = (const float*)d_in[0];
    const int nrows = in_sizes[0] / NC;            // 262144 (multiple of 128)
    const int blocks = nrows / TPB;                // 2048

    // Resolve cuTensorMapEncodeTiled through the runtime (no -lcuda link dep).
    typedef CUresult (*EncodeFn)(CUtensorMap*, CUtensorMapDataType, cuuint32_t, void*,
                                 const cuuint64_t*, const cuuint64_t*, const cuuint32_t*,
                                 const cuuint32_t*, CUtensorMapInterleave, CUtensorMapSwizzle,
                                 CUtensorMapL2promotion, CUtensorMapFloatOOBfill);
    EncodeFn encode = nullptr;
    {
        void* p = nullptr;
        cudaDriverEntryPointQueryResult st;
        if (cudaGetDriverEntryPointByVersion("cuTensorMapEncodeTiled", &p, 12000,
                                             cudaEnableDefault, &st) == cudaSuccess &&
            st == cudaDriverEntryPointSuccess)
            encode = (EncodeFn)p;
    }

    alignas(64) CUtensorMap tmap;
    bool tma_ok = false;
    if (encode) {
        cuuint64_t dims[2]    = {(cuuint64_t)NTOT, (cuuint64_t)nrows};
        cuuint64_t strides[1] = {(cuuint64_t)NTOT * sizeof(float)};   // 2784 B, 16B-multiple
        cuuint32_t box[2]     = {CCOLS, TPB};                         // 96 B x 128 rows
        cuuint32_t estr[2]    = {1, 1};
        tma_ok = (encode(&tmap, CU_TENSOR_MAP_DATA_TYPE_FLOAT32, 2, d_out,
                         dims, strides, box, estr,
                         CU_TENSOR_MAP_INTERLEAVE_NONE, CU_TENSOR_MAP_SWIZZLE_128B,
                         CU_TENSOR_MAP_L2_PROMOTION_L2_128B,
                         CU_TENSOR_MAP_FLOAT_OOB_FILL_NONE) == CUDA_SUCCESS);
    }

    if (tma_ok) {
        algebraic_tma_kernel<<<blocks, TPB, 2 * BUFB>>>(x, tmap);
    } else {
        algebraic_fallback_kernel<<<blocks, TPB>>>(x, (float4*)d_out);
    }
}